// round 17
// baseline (speedup 1.0000x reference)
#include <cuda_runtime.h>
#include <cuda_bf16.h>
#include <math.h>
#include <stdint.h>

// Problem constants (fixed shapes)
#define T_STEPS 2048
#define BATCH   256
#define HID     256
#define OUT_DIM 16

// Scratch (device globals: allocation-free kernel_launch)
__device__ float g_xp[134217728];          // [T][B][H] fp32, 512 MB
__device__ float g_hfinal[BATCH * HID];
__device__ __nv_bfloat16 g_WThi[65536];    // W_ih^T hi: [n][k]
__device__ __nv_bfloat16 g_WTlo[65536];    // W_ih^T lo: [n][k]

// ---------------------------------------------------------------------------
// helpers
// ---------------------------------------------------------------------------
__device__ __forceinline__ uint32_t smem_u32(const void* p) {
    uint32_t a;
    asm("{ .reg .u64 t; cvta.to.shared.u64 t, %1; cvt.u32.u64 %0, t; }"
        : "=r"(a) : "l"(p));
    return a;
}
__device__ __forceinline__ void cp16(uint32_t dst, const void* src) {
    asm volatile("cp.async.cg.shared.global [%0], [%1], 16;"
                 :: "r"(dst), "l"(src) : "memory");
}
__device__ __forceinline__ void ldsm_x4(uint32_t* r, uint32_t addr) {
    asm volatile("ldmatrix.sync.aligned.m8n8.x4.shared.b16 {%0,%1,%2,%3}, [%4];"
                 : "=r"(r[0]), "=r"(r[1]), "=r"(r[2]), "=r"(r[3]) : "r"(addr));
}
__device__ __forceinline__ void ldsm_x2(uint32_t* r, uint32_t addr) {
    asm volatile("ldmatrix.sync.aligned.m8n8.x2.shared.b16 {%0,%1}, [%2];"
                 : "=r"(r[0]), "=r"(r[1]) : "r"(addr));
}
__device__ __forceinline__ void mma_bf16(float* c, const uint32_t* a, const uint32_t* b) {
    asm volatile(
        "mma.sync.aligned.m16n8k16.row.col.f32.bf16.bf16.f32 "
        "{%0,%1,%2,%3}, {%4,%5,%6,%7}, {%8,%9}, {%0,%1,%2,%3};"
        : "+f"(c[0]), "+f"(c[1]), "+f"(c[2]), "+f"(c[3])
        : "r"(a[0]), "r"(a[1]), "r"(a[2]), "r"(a[3]), "r"(b[0]), "r"(b[1]));
}

// f32x2 helpers (ffma2 = 1 issue slot, 4 datapath cycles on B300)
__device__ __forceinline__ unsigned long long f32x2_pack(float x, float y) {
    unsigned long long r;
    asm("mov.b64 %0, {%1, %2};" : "=l"(r) : "r"(__float_as_uint(x)), "r"(__float_as_uint(y)));
    return r;
}
__device__ __forceinline__ void f32x2_unpack(unsigned long long v, float& x, float& y) {
    unsigned int lo, hi;
    asm("mov.b64 {%0, %1}, %2;" : "=r"(lo), "=r"(hi) : "l"(v));
    x = __uint_as_float(lo);
    y = __uint_as_float(hi);
}
__device__ __forceinline__ void ffma2(unsigned long long& acc,
                                      unsigned long long a, unsigned long long b) {
    asm("fma.rn.f32x2 %0, %1, %2, %0;" : "+l"(acc) : "l"(a), "l"(b));
}
__device__ __forceinline__ void fadd2(unsigned long long& acc, unsigned long long b) {
    asm("add.rn.f32x2 %0, %0, %1;" : "+l"(acc) : "l"(b));
}

// fast tanh: 1 - 2/(e^{2x}+1); clamped. ~5 instr (2 MUFU), rel err ~1e-6.
__device__ __forceinline__ float fast_tanh(float x) {
    float xc = fminf(fmaxf(x, -15.f), 15.f);
    float e  = __expf(2.f * xc);
    return 1.f - __fdividef(2.f, e + 1.f);
}

// ---------------------------------------------------------------------------
// Kernel 0: W_ih [k][n] -> transposed bf16 hi/lo [n][k]
// ---------------------------------------------------------------------------
__global__ __launch_bounds__(256)
void prep_w_kernel(const float* __restrict__ Wih) {
    int n = blockIdx.x;
    int k = threadIdx.x;
    float w = Wih[k * 256 + n];
    __nv_bfloat16 hi = __float2bfloat16(w);
    float lof = w - __bfloat162float(hi);
    g_WThi[n * 256 + k] = hi;
    g_WTlo[n * 256 + k] = __float2bfloat16(lof);
}

// ---------------------------------------------------------------------------
// FUSED kernel: recurrence + embedded xp producer on the idle tensor pipe.
// Structure identical to R16; FIX: every cp.async fill is completed by the
// ISSUING thread (wait_group 0) BEFORE the barrier that publishes it.
// (__syncthreads does not wait async-copy groups; only wait_group does.
//  R16 waited on the consumer side after the barrier -> stale-W race.)
//
// smem: W 44*4096=180224 | h 2048 @180224 | X 2048 @182272 |
//       staging @184320: A hi 2560, A lo 2560, B hi 20480, B lo 20480
//       total 230400.
// ---------------------------------------------------------------------------
#define RQ      10                  // reg h-quads (40 rows)
#define SQ      22                  // smem quads per half (88 rows)
#define RH_OFF  180224
#define RX_OFF  182272
#define GST     184320
#define GA_HI   (GST)
#define GA_LO   (GST + 2560)
#define GB_HI   (GST + 5120)
#define GB_LO   (GST + 25600)
#define FSMEM   230400

__global__ __launch_bounds__(256, 1)
void rnn_fused_kernel(const float* __restrict__ W_hh,
                      const float* __restrict__ x,
                      const float* __restrict__ bh) {
    extern __shared__ __align__(16) char sm[];

    const int tid  = threadIdx.x;
    const int lid  = tid & 31;
    const int wrp  = tid >> 5;
    const int half = tid >> 7;
    const int idx  = tid & 127;
    const int jA   = idx;
    const int jB   = idx + 128;
    const int b0   = blockIdx.x * 2;
    const int kbase = half * 128;
    const int wn   = wrp * 32;               // producer warp n-base
    const uint32_t sb = smem_u32(sm);

    // ---- fill W smem: 44 groups; group g: half h=(g>=22), u=g-22h,
    //      rows h*128 + 40 + 4u .. +3; layout [g][j][4] ----
    for (int e = tid; e < 44 * 256; e += 256) {
        int g = e >> 8;
        int j = e & 255;
        int h = (g >= 22) ? 1 : 0;
        int u = g - h * 22;
        int row = h * 128 + 40 + 4 * u;
        float4 v;
        v.x = W_hh[(row + 0) * 256 + j];
        v.y = W_hh[(row + 1) * 256 + j];
        v.z = W_hh[(row + 2) * 256 + j];
        v.w = W_hh[(row + 3) * 256 + j];
        *(float4*)(sm + g * 4096 + j * 16) = v;
    }

    // ---- W register rows [kbase, kbase+40) for cols jA, jB ----
    unsigned long long wA[2 * RQ], wB[2 * RQ];
#pragma unroll
    for (int r = 0; r < 2 * RQ; r++) {
        wA[r] = f32x2_pack(W_hh[(kbase + 2 * r) * 256 + jA],
                           W_hh[(kbase + 2 * r + 1) * 256 + jA]);
        wB[r] = f32x2_pack(W_hh[(kbase + 2 * r) * 256 + jB],
                           W_hh[(kbase + 2 * r + 1) * 256 + jB]);
    }

    // ---- producer bias registers ----
    float2 bias_r[4];
#pragma unroll
    for (int ni = 0; ni < 4; ni++) {
        int n = wn + ni * 8 + (lid & 3) * 2;
        bias_r[ni] = *(const float2*)&bh[n];
    }

    // ---- zero h[2][256] ----
    ((float*)(sm + RH_OFF))[tid] = 0.f;
    ((float*)(sm + RH_OFF))[tid + 256] = 0.f;
    __syncthreads();

    // ---- producer lambdas ----
    float acc[2][4][4];
#pragma unroll
    for (int mi = 0; mi < 2; mi++)
#pragma unroll
        for (int ni = 0; ni < 4; ni++)
#pragma unroll
            for (int e = 0; e < 4; e++) acc[mi][ni][e] = 0.f;

    auto ldA = [&](int win, int c) -> float4 {
        int row = tid >> 3;                  // 0..31
        int bgl = b0 + (row >> 4);
        int tt  = win * 16 + (row & 15);
        int k   = c * 32 + (tid & 7) * 4;
        return *(const float4*)&x[((size_t)bgl * 2048 + tt) * 256 + k];
    };
    auto stAconv = [&](float4 av) {
        int row = tid >> 3;
        int k4b = (tid & 7) * 8;
        __nv_bfloat162 h0 = __float22bfloat162_rn(make_float2(av.x, av.y));
        __nv_bfloat162 h1 = __float22bfloat162_rn(make_float2(av.z, av.w));
        float2 l0 = make_float2(av.x - __bfloat162float(h0.x),
                                av.y - __bfloat162float(h0.y));
        float2 l1 = make_float2(av.z - __bfloat162float(h1.x),
                                av.w - __bfloat162float(h1.y));
        __nv_bfloat162 lo0 = __float22bfloat162_rn(l0);
        __nv_bfloat162 lo1 = __float22bfloat162_rn(l1);
        uint2 hv, lv;
        hv.x = *(uint32_t*)&h0;  hv.y = *(uint32_t*)&h1;
        lv.x = *(uint32_t*)&lo0; lv.y = *(uint32_t*)&lo1;
        *(uint2*)(sm + GA_HI + row * 80 + k4b) = hv;
        *(uint2*)(sm + GA_LO + row * 80 + k4b) = lv;
    };
    auto fillW = [&](int c) {
#pragma unroll
        for (int i = 0; i < 8; i++) {
            int e = tid + i * 256;           // 0..2047
            int s = e >> 10;                 // 0 = hi, 1 = lo
            int rem = e & 1023;
            int n  = rem >> 2;
            int kk = rem & 3;
            const __nv_bfloat16* src =
                (s ? g_WTlo : g_WThi) + n * 256 + c * 32 + kk * 8;
            cp16(sb + (s ? GB_LO : GB_HI) + n * 80 + kk * 16, src);
        }
    };
    auto chunkMMA = [&]() {
#pragma unroll
        for (int t16 = 0; t16 < 2; t16++) {
            uint32_t ah[2][4], al[2][4];
#pragma unroll
            for (int mi = 0; mi < 2; mi++) {
                uint32_t a = sb + (uint32_t)((mi * 16 + (lid & 15)) * 80 +
                                             (lid >> 4) * 16 + t16 * 32);
                ldsm_x4(ah[mi], a + GA_HI);
                ldsm_x4(al[mi], a + GA_LO);
            }
#pragma unroll
            for (int ni = 0; ni < 4; ni++) {
                uint32_t bh2[2], bl2[2];
                uint32_t ba = sb + (uint32_t)((wn + ni * 8 + (lid & 7)) * 80 +
                                              ((lid >> 3) & 1) * 16 + t16 * 32);
                ldsm_x2(bh2, ba + GB_HI);
                ldsm_x2(bl2, ba + GB_LO);
#pragma unroll
                for (int mi = 0; mi < 2; mi++) {
                    mma_bf16(acc[mi][ni], ah[mi], bh2);
                    mma_bf16(acc[mi][ni], al[mi], bh2);
                    mma_bf16(acc[mi][ni], ah[mi], bl2);
                }
            }
        }
    };
    auto epilogue = [&](int win) {
        int T0 = win * 16;
        int tt1 = lid >> 2;
#pragma unroll
        for (int mi = 0; mi < 2; mi++) {
            int bgl = b0 + mi;
#pragma unroll
            for (int ni = 0; ni < 4; ni++) {
                int n = wn + ni * 8 + (lid & 3) * 2;
                float2 bs = bias_r[ni];
                size_t a1 = ((size_t)(T0 + tt1) * BATCH + bgl) * HID + n;
                *(float2*)&g_xp[a1] =
                    make_float2(acc[mi][ni][0] + bs.x, acc[mi][ni][1] + bs.y);
                size_t a2 = ((size_t)(T0 + tt1 + 8) * BATCH + bgl) * HID + n;
                *(float2*)&g_xp[a2] =
                    make_float2(acc[mi][ni][2] + bs.x, acc[mi][ni][3] + bs.y);
                acc[mi][ni][0] = acc[mi][ni][1] = 0.f;
                acc[mi][ni][2] = acc[mi][ni][3] = 0.f;
            }
        }
    };

    // ---- prologue: produce windows 0 and 1 serially; pre-fill chunk 0 of w2 ----
    for (int w = 0; w < 2; w++) {
        for (int c = 0; c < 8; c++) {
            float4 av = ldA(w, c);
            stAconv(av);
            fillW(c);
            asm volatile("cp.async.commit_group;" ::: "memory");
            asm volatile("cp.async.wait_group 0;" ::: "memory");
            __syncthreads();
            chunkMMA();
            __syncthreads();
        }
        epilogue(w);
    }
    {
        float4 av = ldA(2, 0);
        stAconv(av);
        fillW(0);
        asm volatile("cp.async.commit_group;" ::: "memory");
        asm volatile("cp.async.wait_group 0;" ::: "memory");   // FIX: complete before publish
    }
    __syncthreads();

    // ---- recurrence state ----
    const float* xpA = g_xp + (size_t)(b0 + half) * HID + jA;
    float pA = xpA[0];
    float pB = xpA[128];

    const char* hb0  = sm + RH_OFF + kbase * 4;
    const char* hb1  = sm + RH_OFF + 1024 + kbase * 4;
    const char* wsmA = sm + (half * SQ) * 4096 + jA * 16;
    const char* wsmB = sm + (half * SQ) * 4096 + jB * 16;

    float hA = 0.f, hB = 0.f;

    for (int t = 0; t < T_STEPS; t++) {
        const int v  = t >> 4;
        const int pm = t & 15;
        const int pw = v + 2;
        const bool prod = (pw < 128);

        // ---- S1: producer tensor work (overlaps the fp32 k-loop below) ----
        if (prod) {
            if (pm < 8) {
                chunkMMA();                  // staging published at prev barrier2
            } else if (pm == 8) {
                epilogue(pw);
            }
        }
        // A-preload for the fill placed at S4
        int fw = -1, fc = 0;
        if (prod) {
            if (pm < 7)                        { fw = pw;     fc = pm + 1; }
            else if (pm == 15 && pw + 1 < 128) { fw = pw + 1; fc = 0; }
        }
        float4 av = make_float4(0.f, 0.f, 0.f, 0.f);
        if (fw >= 0) av = ldA(fw, fc);

        // ---- recurrence: xp prefetch + k-loop ----
        unsigned long long aA0x = 0, aA0y = 0, aA1x = 0, aA1y = 0;
        unsigned long long aB0x = 0, aB0y = 0, aB1x = 0, aB1y = 0;

        int tn = (t + 1 < T_STEPS) ? (t + 1) : t;
        float pAn = xpA[(size_t)tn * (BATCH * HID)];
        float pBn = xpA[(size_t)tn * (BATCH * HID) + 128];

#pragma unroll
        for (int q = 0; q < RQ; q++) {
            ulonglong2 h0 = *(const ulonglong2*)(hb0 + q * 16);
            ulonglong2 h1 = *(const ulonglong2*)(hb1 + q * 16);
            ffma2(aA0x, h0.x, wA[2 * q]);
            ffma2(aA0y, h0.y, wA[2 * q + 1]);
            ffma2(aA1x, h1.x, wA[2 * q]);
            ffma2(aA1y, h1.y, wA[2 * q + 1]);
            ffma2(aB0x, h0.x, wB[2 * q]);
            ffma2(aB0y, h0.y, wB[2 * q + 1]);
            ffma2(aB1x, h1.x, wB[2 * q]);
            ffma2(aB1y, h1.y, wB[2 * q + 1]);
        }
#pragma unroll
        for (int u = 0; u < SQ; u++) {
            ulonglong2 wqA = *(const ulonglong2*)(wsmA + u * 4096);
            ulonglong2 wqB = *(const ulonglong2*)(wsmB + u * 4096);
            ulonglong2 h0  = *(const ulonglong2*)(hb0 + 160 + u * 16);
            ulonglong2 h1  = *(const ulonglong2*)(hb1 + 160 + u * 16);
            ffma2(aA0x, h0.x, wqA.x);
            ffma2(aA0y, h0.y, wqA.y);
            ffma2(aA1x, h1.x, wqA.x);
            ffma2(aA1y, h1.y, wqA.y);
            ffma2(aB0x, h0.x, wqB.x);
            ffma2(aB0y, h0.y, wqB.y);
            ffma2(aB1x, h1.x, wqB.x);
            ffma2(aB1y, h1.y, wqB.y);
        }

        fadd2(aA0x, aA0y);
        fadd2(aA1x, aA1y);
        fadd2(aB0x, aB0y);
        fadd2(aB1x, aB1y);
        float lo, hi;
        f32x2_unpack(aA0x, lo, hi); float sA0 = lo + hi;
        f32x2_unpack(aA1x, lo, hi); float sA1 = lo + hi;
        f32x2_unpack(aB0x, lo, hi); float sB0 = lo + hi;
        f32x2_unpack(aB1x, lo, hi); float sB1 = lo + hi;

        // exchange: publish the OTHER batch's partials
        float2* xb = (float2*)(sm + RX_OFF + half * 1024) + idx;
        *xb = (half == 0) ? make_float2(sA1, sB1) : make_float2(sA0, sB0);
        __syncthreads();   // barrier1: X visible; staging reads (S1) retired

        // ---- S4: producer fills; MUST complete before barrier2 publishes ----
        if (fw >= 0) {
            stAconv(av);
            fillW(fc);
            asm volatile("cp.async.commit_group;" ::: "memory");
            asm volatile("cp.async.wait_group 0;" ::: "memory");  // FIX
        }

        // ---- finalize ----
        float2 other = *((const float2*)(sm + RX_OFF + (half ^ 1) * 1024) + idx);
        float totA = ((half == 0) ? sA0 : sA1) + other.x + pA;
        float totB = ((half == 0) ? sB0 : sB1) + other.y + pB;
        hA = fast_tanh(totA);
        hB = fast_tanh(totB);
        pA = pAn;
        pB = pBn;
        float* hrow = (float*)(sm + RH_OFF + half * 1024);
        hrow[jA] = hA;
        hrow[jB] = hB;
        __syncthreads();   // barrier2: h AND completed staging visible
    }

    g_hfinal[(size_t)(b0 + half) * HID + jA] = hA;
    g_hfinal[(size_t)(b0 + half) * HID + jB] = hB;
}

// ---------------------------------------------------------------------------
// Kernel 3: classifier head (tiny)
// ---------------------------------------------------------------------------
__global__ __launch_bounds__(128)
void rnn_head_kernel(const float* __restrict__ fcw,
                     const float* __restrict__ fcb,
                     float* __restrict__ out) {
    __shared__ float hs[HID];
    __shared__ float part[8][OUT_DIM];
    const int b = blockIdx.x;
    const int tid = threadIdx.x;

    hs[tid]       = g_hfinal[(size_t)b * HID + tid];
    hs[tid + 128] = g_hfinal[(size_t)b * HID + tid + 128];
    __syncthreads();

    const int o   = tid & 15;
    const int seg = tid >> 4;
    float s = 0.f;
#pragma unroll
    for (int jj = 0; jj < 32; jj++) {
        int j = seg * 32 + jj;
        s += hs[j] * fcw[o * HID + j];
    }
    part[seg][o] = s;
    __syncthreads();
    if (tid < OUT_DIM) {
        float r = fcb[tid];
#pragma unroll
        for (int sg = 0; sg < 8; sg++) r += part[sg][tid];
        out[b * OUT_DIM + tid] = r;
    }
}

// ---------------------------------------------------------------------------
extern "C" void kernel_launch(void* const* d_in, const int* in_sizes, int n_in,
                              void* d_out, int out_size) {
    const float* x   = (const float*)d_in[0];
    const float* Wih = (const float*)d_in[1];
    const float* Whh = (const float*)d_in[2];
    const float* bh  = (const float*)d_in[3];
    const float* fcw = (const float*)d_in[4];
    const float* fcb = (const float*)d_in[5];
    float* out = (float*)d_out;

    // 0) bf16 hi/lo split of W_ih^T (read by the fused producer)
    prep_w_kernel<<<256, 256>>>(Wih);

    // 1) fused: recurrence + embedded xp production on the tensor pipe
    cudaFuncSetAttribute(rnn_fused_kernel,
                         cudaFuncAttributeMaxDynamicSharedMemorySize, FSMEM);
    rnn_fused_kernel<<<BATCH / 2, 256, FSMEM>>>(Whh, x, bh);

    // 2) classifier head
    rnn_head_kernel<<<BATCH, 128>>>(fcw, fcb, out);
}